// round 16
// baseline (speedup 1.0000x reference)
#include <cuda_runtime.h>
#include <cstdint>

// VectorQuantizer: distance GEMM on the tensor pipe via warp-level mma.sync
// (tcgen05 is unavailable: harness compiles via compute_103 PTX, which ptxas
// rejects for tcgen05; mma.sync tf32 is arch-unconditional PTX, sm_80+).
//
// 3xTF32 split: dot(z,e) = a0b0 + a0b1 + a1b0 concatenated along K -> one
// K'=192 tf32 GEMM, fp32 accumulation. Dot abs-error ~1e-9 == validated
// scalar kernel's class (zero argmin flips at rel_err 4.36516e-5).
// d = fl(fl(zz+ee) - 2*dot), ascending k, strict <, cross-lane tie -> min idx.

typedef uint32_t u32;

#define B_      16
#define C_      64
#define HW_     4096
#define N_      (B_ * HW_)          // 65536 vectors
#define NE_     1024
#define D_      64
#define TPB     256                 // 8 warps
#define VPB     128                 // vectors per block (warp: 16)
#define NBLK    (N_ / VPB)          // 512
#define KS      24                  // K'=192 -> 24 k-steps of 8
#define NCHUNK  16                  // 16 chunks of 64 entries
#define CHUNK_U32 12288             // B' u32 words per chunk (64*192)

// dynamic smem layout (bytes)
#define OFF_B    0                  // uint4[3072]  = 49152
#define OFF_Z    49152              // float[64*136]= 34816
#define OFF_EE   83968              // float[1024]  = 4096
#define OFF_RED  88064              // double[256]  = 2048
#define OFF_ZZ   90112              // float[128]   = 512
#define OFF_BEST 90624              // int[128]     = 512
#define SMEM_TOTAL 91136
#define SZP 136                     // s_z row pitch (136 % 32 == 8 -> conflict-free frag gather)

__device__ double   g_partial[NBLK];
__device__ unsigned g_done;                       // zero-init; reset each run
__device__ float    g_ee[NE_];
__device__ u32      g_bfrag[NCHUNK * CHUNK_U32];  // 786 KB, fragment-ordered B'

__device__ __forceinline__ u32 f2tf32(float x) {
    u32 u;
    asm("cvt.rna.tf32.f32 %0, %1;" : "=r"(u) : "f"(x));
    return u;   // low 13 bits zero -> reinterpret as f32 == rounded value
}

#define MMA_TF32(c, a0, a1, a2, a3, b0, b1)                                   \
    asm volatile("mma.sync.aligned.m16n8k8.row.col.f32.tf32.tf32.f32 "        \
                 "{%0,%1,%2,%3}, {%4,%5,%6,%7}, {%8,%9}, {%0,%1,%2,%3};"       \
                 : "+f"((c)[0]), "+f"((c)[1]), "+f"((c)[2]), "+f"((c)[3])      \
                 : "r"(a0), "r"(a1), "r"(a2), "r"(a3), "r"(b0), "r"(b1))

// ---- prep: ee (validated fmaf order) + B' split in mma fragment layout ----
// B' k-groups: [0,64)=e0, [64,128)=e1, [128,192)=e0  (A' = [a0, a0, a1])
__global__ void vq_prep_kernel(const float* __restrict__ cb) {
    int n = blockIdx.x * blockDim.x + threadIdx.x;
    if (n >= NE_) return;
    const float4* ep = (const float4*)(cb + (size_t)n * D_);
    float s = 0.f;
#pragma unroll
    for (int c4 = 0; c4 < D_ / 4; c4++) {
        float4 v = ep[c4];
        s = fmaf(v.x, v.x, s); s = fmaf(v.y, v.y, s);
        s = fmaf(v.z, v.z, s); s = fmaf(v.w, v.w, s);
    }
    g_ee[n] = s;

    const int chunk = n >> 6, e = n & 63;
    const int u = e >> 3, gcol = e & 7;
    const int tp = u >> 1, half = u & 1;
    const float* row = cb + (size_t)n * D_;
#pragma unroll 1
    for (int kp = 0; kp < 192; kp++) {
        const int grp = kp >> 6, dim = kp & 63;
        float x = row[dim];
        u32 h = f2tf32(x);
        u32 val = h;
        if (grp == 1) { float r = x - __uint_as_float(h); val = f2tf32(r); }
        const int tig = kp & 3, rr = (kp >> 2) & 1, ss = kp >> 3;
        const int lane = gcol * 4 + tig;
        g_bfrag[(((chunk * 4 + tp) * KS + ss) * 32 + lane) * 4 + half * 2 + rr] = val;
    }
}

// ---- main ----
__global__ __launch_bounds__(TPB) void vq_tc_kernel(
    const float* __restrict__ z, const float* __restrict__ cb,
    float* __restrict__ out, int write_zq, int loss_idx)
{
    extern __shared__ __align__(16) unsigned char smem[];
    uint4*  s_b    = (uint4*)(smem + OFF_B);
    float*  s_z    = (float*)(smem + OFF_Z);
    float*  s_ee   = (float*)(smem + OFF_EE);
    double* s_red  = (double*)(smem + OFF_RED);
    float*  s_zz   = (float*)(smem + OFF_ZZ);
    int*    s_best = (int*)(smem + OFF_BEST);

    const int tid  = threadIdx.x;
    const int wid  = tid >> 5;
    const int lane = tid & 31;
    const int g    = lane >> 2;
    const int tig  = lane & 3;

    const int  bblk = (blockIdx.x * VPB) / HW_;
    const int  hw0  = (blockIdx.x * VPB) % HW_;
    const float* zsrc = z + (size_t)bblk * (C_ * HW_) + hw0;

    // stage z slab [64 c][128 hw] -> s_z, and ee -> s_ee
    {
        const float4* zs4 = (const float4*)zsrc;
#pragma unroll
        for (int i = 0; i < 8; i++) {
            int idx = tid + i * TPB;           // 2048 float4
            int c = idx >> 5, p = idx & 31;
            float4 v = zs4[c * (HW_ / 4) + p];
            float* dst = s_z + c * SZP + p * 4;
            dst[0] = v.x; dst[1] = v.y; dst[2] = v.z; dst[3] = v.w;
        }
#pragma unroll
        for (int i = 0; i < NE_ / TPB; i++) s_ee[tid + i * TPB] = g_ee[tid + i * TPB];
    }
    __syncthreads();

    // zz per vector (validated sequential fmaf, ascending c)
    if (tid < VPB) {
        float zzv = 0.f;
#pragma unroll
        for (int c = 0; c < D_; c++) {
            float xv = s_z[c * SZP + tid];
            zzv = fmaf(xv, xv, zzv);
        }
        s_zz[tid] = zzv;
    }

    // A fragments in registers: warp owns rows [wid*16, wid*16+16)
    const int row0 = wid * 16 + g;
    const int row1 = row0 + 8;
    u32 z0a[16], z1a[16], z0b[16], z1b[16];
#pragma unroll
    for (int dd = 0; dd < 16; dd++) {
        const int dim = 4 * dd + tig;
        float x0 = s_z[dim * SZP + row0];
        float x1 = s_z[dim * SZP + row1];
        u32 h0 = f2tf32(x0); float r0 = x0 - __uint_as_float(h0);
        u32 h1 = f2tf32(x1); float r1 = x1 - __uint_as_float(h1);
        z0a[dd] = h0; z1a[dd] = f2tf32(r0);
        z0b[dd] = h1; z1b[dd] = f2tf32(r1);
    }
    __syncthreads();
    const float zz0 = s_zz[row0];
    const float zz1 = s_zz[row1];

    float bd0 = 3.402823466e38f, bd1 = 3.402823466e38f;
    int   bi0 = 0,               bi1 = 0;

    for (int chunk = 0; chunk < NCHUNK; chunk++) {
        __syncthreads();
        {   // stage B' chunk (fragment-ordered, linear copy)
            const uint4* src = (const uint4*)g_bfrag + chunk * (CHUNK_U32 / 4);
#pragma unroll
            for (int i = 0; i < 12; i++)
                s_b[tid + i * TPB] = src[tid + i * TPB];
        }
        __syncthreads();

        float acc[8][4];
#pragma unroll
        for (int uu = 0; uu < 8; uu++) {
            acc[uu][0] = 0.f; acc[uu][1] = 0.f; acc[uu][2] = 0.f; acc[uu][3] = 0.f;
        }

#pragma unroll
        for (int s = 0; s < KS; s++) {
            const int sm = s & 7;
            u32 a0, a1, a2, a3;
            if (s < 16) { a0 = z0a[2*sm]; a1 = z0b[2*sm]; a2 = z0a[2*sm+1]; a3 = z0b[2*sm+1]; }
            else        { a0 = z1a[2*sm]; a1 = z1b[2*sm]; a2 = z1a[2*sm+1]; a3 = z1b[2*sm+1]; }
#pragma unroll
            for (int tp = 0; tp < 4; tp++) {
                uint4 bb = s_b[(tp * KS + s) * 32 + lane];
                MMA_TF32(acc[2*tp],     a0, a1, a2, a3, bb.x, bb.y);
                MMA_TF32(acc[2*tp + 1], a0, a1, a2, a3, bb.z, bb.w);
            }
        }

        // d-epilogue: validated structure, ascending entry index
        const int cb0 = chunk * 64;
#pragma unroll
        for (int uu = 0; uu < 8; uu++) {
            const int n1 = cb0 + uu * 8 + 2 * tig;
            const float ee1 = s_ee[n1], ee2 = s_ee[n1 + 1];
            float d;
            d = __fadd_rn(__fadd_rn(zz0, ee1), -2.0f * acc[uu][0]);
            if (d < bd0) { bd0 = d; bi0 = n1; }
            d = __fadd_rn(__fadd_rn(zz0, ee2), -2.0f * acc[uu][1]);
            if (d < bd0) { bd0 = d; bi0 = n1 + 1; }
            d = __fadd_rn(__fadd_rn(zz1, ee1), -2.0f * acc[uu][2]);
            if (d < bd1) { bd1 = d; bi1 = n1; }
            d = __fadd_rn(__fadd_rn(zz1, ee2), -2.0f * acc[uu][3]);
            if (d < bd1) { bd1 = d; bi1 = n1 + 1; }
        }
    }

    // cross-lane combine within quad (same rows): min d, tie -> min index
#pragma unroll
    for (int off = 1; off <= 2; off <<= 1) {
        float d2; int i2;
        d2 = __shfl_xor_sync(0xffffffffu, bd0, off);
        i2 = __shfl_xor_sync(0xffffffffu, bi0, off);
        if (d2 < bd0 || (d2 == bd0 && i2 < bi0)) { bd0 = d2; bi0 = i2; }
        d2 = __shfl_xor_sync(0xffffffffu, bd1, off);
        i2 = __shfl_xor_sync(0xffffffffu, bi1, off);
        if (d2 < bd1 || (d2 == bd1 && i2 < bi1)) { bd1 = d2; bi1 = i2; }
    }
    if (tig == 0) {
        s_best[row0] = bi0;
        s_best[row1] = bi1;
    }
    __syncthreads();

    // epilogue: z_q write + fp64 loss. thread -> (vector v, channel half)
    const int v = tid & 127, half = tid >> 7, c0 = half * 32;
    const int bi = s_best[v];
    const float* ev = cb + (size_t)bi * D_;
    float* ob = out + (size_t)bblk * (C_ * HW_) + hw0 + v;
    double lsum = 0.0;
#pragma unroll
    for (int c = c0; c < c0 + 32; c++) {
        float e  = __ldg(ev + c);
        float zv = s_z[c * SZP + v];
        float df = e - zv;
        lsum += (double)df * (double)df;
        if (write_zq) ob[(size_t)c * HW_] = e;
    }

#pragma unroll
    for (int off = 16; off; off >>= 1)
        lsum += __shfl_down_sync(0xffffffffu, lsum, off);
    if (lane == 0) s_red[wid] = lsum;
    __syncthreads();
    if (tid == 0) {
        double t = 0.0;
#pragma unroll
        for (int w = 0; w < 8; w++) t += s_red[w];
        g_partial[blockIdx.x] = t;
    }

    if (loss_idx < 0) return;

    // last-block-done deterministic finalize over 512 partials
    __shared__ unsigned s_is_last;
    if (tid == 0) {
        __threadfence();
        s_is_last = (atomicAdd(&g_done, 1u) == NBLK - 1) ? 1u : 0u;
    }
    __syncthreads();
    if (s_is_last) {
        __threadfence();
        double s = g_partial[tid] + g_partial[tid + 256];
        s_red[tid] = s;
        __syncthreads();
#pragma unroll
        for (int off = 128; off; off >>= 1) {
            if (tid < off) s_red[tid] = s_red[tid] + s_red[tid + off];
            __syncthreads();
        }
        if (tid == 0) {
            float m = (float)(s_red[0] / (double)((long long)N_ * D_));
            out[loss_idx] = 0.25f * m + m;
            g_done = 0;
        }
    }
}

extern "C" void kernel_launch(void* const* d_in, const int* in_sizes, int n_in,
                              void* d_out, int out_size) {
    const float* z  = (const float*)d_in[0];
    const float* cb = (const float*)d_in[1];
    float* out = (float*)d_out;

    const int zq_elems = N_ * C_;               // 1048576
    const int write_zq = (out_size >= zq_elems) ? 1 : 0;
    int loss_idx = -1;
    if (out_size == 1)            loss_idx = 0;
    else if (out_size > zq_elems) loss_idx = zq_elems;

    static int attr_done = 0;
    if (!attr_done) {
        cudaFuncSetAttribute(vq_tc_kernel,
                             cudaFuncAttributeMaxDynamicSharedMemorySize, SMEM_TOTAL);
        attr_done = 1;
    }

    vq_prep_kernel<<<NE_ / 256, 256>>>(cb);
    vq_tc_kernel<<<NBLK, TPB, SMEM_TOTAL>>>(z, cb, out, write_zq, loss_idx);
}

// round 17
// speedup vs baseline: 1.0047x; 1.0047x over previous
#include <cuda_runtime.h>
#include <cstdint>

// VectorQuantizer: distance GEMM on the tensor pipe via warp-level mma.sync
// (tcgen05 is unavailable: harness compiles via compute_103 PTX, which ptxas
// rejects for tcgen05; mma.sync tf32 is arch-unconditional PTX, sm_80+).
//
// 3xTF32 split: dot(z,e) = a0b0 + a0b1 + a1b0 concatenated along K -> one
// K'=192 tf32 GEMM, fp32 accumulation. Dot abs-error ~1e-9 == validated
// scalar kernel's class (zero argmin flips at rel_err 4.36516e-5).
// d = fl(fl(zz+ee) - 2*dot), ascending k, strict <, cross-lane tie -> min idx.

typedef uint32_t u32;

#define B_      16
#define C_      64
#define HW_     4096
#define N_      (B_ * HW_)          // 65536 vectors
#define NE_     1024
#define D_      64
#define TPB     256                 // 8 warps
#define VPB     128                 // vectors per block (warp: 16)
#define NBLK    (N_ / VPB)          // 512
#define KS      24                  // K'=192 -> 24 k-steps of 8
#define NCHUNK  16                  // 16 chunks of 64 entries
#define CHUNK_U32 12288             // B' u32 words per chunk (64*192)

// dynamic smem layout (bytes)
#define OFF_B    0                  // uint4[3072]  = 49152
#define OFF_Z    49152              // float[64*136]= 34816
#define OFF_EE   83968              // float[1024]  = 4096
#define OFF_RED  88064              // double[256]  = 2048
#define OFF_ZZ   90112              // float[128]   = 512
#define OFF_BEST 90624              // int[128]     = 512
#define SMEM_TOTAL 91136
#define SZP 136                     // s_z row pitch (136 % 32 == 8 -> conflict-free frag gather)

__device__ double   g_partial[NBLK];
__device__ unsigned g_done;                       // zero-init; reset each run
__device__ float    g_ee[NE_];
__device__ u32      g_bfrag[NCHUNK * CHUNK_U32];  // 786 KB, fragment-ordered B'

__device__ __forceinline__ u32 f2tf32(float x) {
    u32 u;
    asm("cvt.rna.tf32.f32 %0, %1;" : "=r"(u) : "f"(x));
    return u;   // low 13 bits zero -> reinterpret as f32 == rounded value
}

#define MMA_TF32(c, a0, a1, a2, a3, b0, b1)                                   \
    asm volatile("mma.sync.aligned.m16n8k8.row.col.f32.tf32.tf32.f32 "        \
                 "{%0,%1,%2,%3}, {%4,%5,%6,%7}, {%8,%9}, {%0,%1,%2,%3};"       \
                 : "+f"((c)[0]), "+f"((c)[1]), "+f"((c)[2]), "+f"((c)[3])      \
                 : "r"(a0), "r"(a1), "r"(a2), "r"(a3), "r"(b0), "r"(b1))

// ---- prep: ee (validated fmaf order) + B' split in mma fragment layout ----
// B' k-groups: [0,64)=e0, [64,128)=e1, [128,192)=e0  (A' = [a0, a0, a1])
__global__ void vq_prep_kernel(const float* __restrict__ cb) {
    int n = blockIdx.x * blockDim.x + threadIdx.x;
    if (n >= NE_) return;
    const float4* ep = (const float4*)(cb + (size_t)n * D_);
    float s = 0.f;
#pragma unroll
    for (int c4 = 0; c4 < D_ / 4; c4++) {
        float4 v = ep[c4];
        s = fmaf(v.x, v.x, s); s = fmaf(v.y, v.y, s);
        s = fmaf(v.z, v.z, s); s = fmaf(v.w, v.w, s);
    }
    g_ee[n] = s;

    const int chunk = n >> 6, e = n & 63;
    const int u = e >> 3, gcol = e & 7;
    const int tp = u >> 1, half = u & 1;
    const float* row = cb + (size_t)n * D_;
#pragma unroll 1
    for (int kp = 0; kp < 192; kp++) {
        const int grp = kp >> 6, dim = kp & 63;
        float x = row[dim];
        u32 h = f2tf32(x);
        u32 val = h;
        if (grp == 1) { float r = x - __uint_as_float(h); val = f2tf32(r); }
        const int tig = kp & 3, rr = (kp >> 2) & 1, ss = kp >> 3;
        const int lane = gcol * 4 + tig;
        g_bfrag[(((chunk * 4 + tp) * KS + ss) * 32 + lane) * 4 + half * 2 + rr] = val;
    }
}

// ---- main ----
__global__ __launch_bounds__(TPB) void vq_tc_kernel(
    const float* __restrict__ z, const float* __restrict__ cb,
    float* __restrict__ out, int write_zq, int loss_idx)
{
    extern __shared__ __align__(16) unsigned char smem[];
    uint4*  s_b    = (uint4*)(smem + OFF_B);
    float*  s_z    = (float*)(smem + OFF_Z);
    float*  s_ee   = (float*)(smem + OFF_EE);
    double* s_red  = (double*)(smem + OFF_RED);
    float*  s_zz   = (float*)(smem + OFF_ZZ);
    int*    s_best = (int*)(smem + OFF_BEST);

    const int tid  = threadIdx.x;
    const int wid  = tid >> 5;
    const int lane = tid & 31;
    const int g    = lane >> 2;
    const int tig  = lane & 3;

    const int  bblk = (blockIdx.x * VPB) / HW_;
    const int  hw0  = (blockIdx.x * VPB) % HW_;
    const float* zsrc = z + (size_t)bblk * (C_ * HW_) + hw0;

    // stage z slab [64 c][128 hw] -> s_z, and ee -> s_ee
    {
        const float4* zs4 = (const float4*)zsrc;
#pragma unroll
        for (int i = 0; i < 8; i++) {
            int idx = tid + i * TPB;           // 2048 float4
            int c = idx >> 5, p = idx & 31;
            float4 v = zs4[c * (HW_ / 4) + p];
            float* dst = s_z + c * SZP + p * 4;
            dst[0] = v.x; dst[1] = v.y; dst[2] = v.z; dst[3] = v.w;
        }
#pragma unroll
        for (int i = 0; i < NE_ / TPB; i++) s_ee[tid + i * TPB] = g_ee[tid + i * TPB];
    }
    __syncthreads();

    // zz per vector (validated sequential fmaf, ascending c)
    if (tid < VPB) {
        float zzv = 0.f;
#pragma unroll
        for (int c = 0; c < D_; c++) {
            float xv = s_z[c * SZP + tid];
            zzv = fmaf(xv, xv, zzv);
        }
        s_zz[tid] = zzv;
    }

    // A fragments in registers: warp owns rows [wid*16, wid*16+16)
    const int row0 = wid * 16 + g;
    const int row1 = row0 + 8;
    u32 z0a[16], z1a[16], z0b[16], z1b[16];
#pragma unroll
    for (int dd = 0; dd < 16; dd++) {
        const int dim = 4 * dd + tig;
        float x0 = s_z[dim * SZP + row0];
        float x1 = s_z[dim * SZP + row1];
        u32 h0 = f2tf32(x0); float r0 = x0 - __uint_as_float(h0);
        u32 h1 = f2tf32(x1); float r1 = x1 - __uint_as_float(h1);
        z0a[dd] = h0; z1a[dd] = f2tf32(r0);
        z0b[dd] = h1; z1b[dd] = f2tf32(r1);
    }
    __syncthreads();
    const float zz0 = s_zz[row0];
    const float zz1 = s_zz[row1];

    float bd0 = 3.402823466e38f, bd1 = 3.402823466e38f;
    int   bi0 = 0,               bi1 = 0;

    for (int chunk = 0; chunk < NCHUNK; chunk++) {
        __syncthreads();
        {   // stage B' chunk (fragment-ordered, linear copy)
            const uint4* src = (const uint4*)g_bfrag + chunk * (CHUNK_U32 / 4);
#pragma unroll
            for (int i = 0; i < 12; i++)
                s_b[tid + i * TPB] = src[tid + i * TPB];
        }
        __syncthreads();

        float acc[8][4];
#pragma unroll
        for (int uu = 0; uu < 8; uu++) {
            acc[uu][0] = 0.f; acc[uu][1] = 0.f; acc[uu][2] = 0.f; acc[uu][3] = 0.f;
        }

#pragma unroll
        for (int s = 0; s < KS; s++) {
            const int sm = s & 7;
            u32 a0, a1, a2, a3;
            if (s < 16) { a0 = z0a[2*sm]; a1 = z0b[2*sm]; a2 = z0a[2*sm+1]; a3 = z0b[2*sm+1]; }
            else        { a0 = z1a[2*sm]; a1 = z1b[2*sm]; a2 = z1a[2*sm+1]; a3 = z1b[2*sm+1]; }
#pragma unroll
            for (int tp = 0; tp < 4; tp++) {
                uint4 bb = s_b[(tp * KS + s) * 32 + lane];
                MMA_TF32(acc[2*tp],     a0, a1, a2, a3, bb.x, bb.y);
                MMA_TF32(acc[2*tp + 1], a0, a1, a2, a3, bb.z, bb.w);
            }
        }

        // d-epilogue: validated structure, ascending entry index
        const int cb0 = chunk * 64;
#pragma unroll
        for (int uu = 0; uu < 8; uu++) {
            const int n1 = cb0 + uu * 8 + 2 * tig;
            const float ee1 = s_ee[n1], ee2 = s_ee[n1 + 1];
            float d;
            d = __fadd_rn(__fadd_rn(zz0, ee1), -2.0f * acc[uu][0]);
            if (d < bd0) { bd0 = d; bi0 = n1; }
            d = __fadd_rn(__fadd_rn(zz0, ee2), -2.0f * acc[uu][1]);
            if (d < bd0) { bd0 = d; bi0 = n1 + 1; }
            d = __fadd_rn(__fadd_rn(zz1, ee1), -2.0f * acc[uu][2]);
            if (d < bd1) { bd1 = d; bi1 = n1; }
            d = __fadd_rn(__fadd_rn(zz1, ee2), -2.0f * acc[uu][3]);
            if (d < bd1) { bd1 = d; bi1 = n1 + 1; }
        }
    }

    // cross-lane combine within quad (same rows): min d, tie -> min index
#pragma unroll
    for (int off = 1; off <= 2; off <<= 1) {
        float d2; int i2;
        d2 = __shfl_xor_sync(0xffffffffu, bd0, off);
        i2 = __shfl_xor_sync(0xffffffffu, bi0, off);
        if (d2 < bd0 || (d2 == bd0 && i2 < bi0)) { bd0 = d2; bi0 = i2; }
        d2 = __shfl_xor_sync(0xffffffffu, bd1, off);
        i2 = __shfl_xor_sync(0xffffffffu, bi1, off);
        if (d2 < bd1 || (d2 == bd1 && i2 < bi1)) { bd1 = d2; bi1 = i2; }
    }
    if (tig == 0) {
        s_best[row0] = bi0;
        s_best[row1] = bi1;
    }
    __syncthreads();

    // epilogue: z_q write + fp64 loss. thread -> (vector v, channel half)
    const int v = tid & 127, half = tid >> 7, c0 = half * 32;
    const int bi = s_best[v];
    const float* ev = cb + (size_t)bi * D_;
    float* ob = out + (size_t)bblk * (C_ * HW_) + hw0 + v;
    double lsum = 0.0;
#pragma unroll
    for (int c = c0; c < c0 + 32; c++) {
        float e  = __ldg(ev + c);
        float zv = s_z[c * SZP + v];
        float df = e - zv;
        lsum += (double)df * (double)df;
        if (write_zq) ob[(size_t)c * HW_] = e;
    }

#pragma unroll
    for (int off = 16; off; off >>= 1)
        lsum += __shfl_down_sync(0xffffffffu, lsum, off);
    if (lane == 0) s_red[wid] = lsum;
    __syncthreads();
    if (tid == 0) {
        double t = 0.0;
#pragma unroll
        for (int w = 0; w < 8; w++) t += s_red[w];
        g_partial[blockIdx.x] = t;
    }

    if (loss_idx < 0) return;

    // last-block-done deterministic finalize over 512 partials
    __shared__ unsigned s_is_last;
    if (tid == 0) {
        __threadfence();
        s_is_last = (atomicAdd(&g_done, 1u) == NBLK - 1) ? 1u : 0u;
    }
    __syncthreads();
    if (s_is_last) {
        __threadfence();
        double s = g_partial[tid] + g_partial[tid + 256];
        s_red[tid] = s;
        __syncthreads();
#pragma unroll
        for (int off = 128; off; off >>= 1) {
            if (tid < off) s_red[tid] = s_red[tid] + s_red[tid + off];
            __syncthreads();
        }
        if (tid == 0) {
            float m = (float)(s_red[0] / (double)((long long)N_ * D_));
            out[loss_idx] = 0.25f * m + m;
            g_done = 0;
        }
    }
}

extern "C" void kernel_launch(void* const* d_in, const int* in_sizes, int n_in,
                              void* d_out, int out_size) {
    const float* z  = (const float*)d_in[0];
    const float* cb = (const float*)d_in[1];
    float* out = (float*)d_out;

    const int zq_elems = N_ * C_;               // 1048576
    const int write_zq = (out_size >= zq_elems) ? 1 : 0;
    int loss_idx = -1;
    if (out_size == 1)            loss_idx = 0;
    else if (out_size > zq_elems) loss_idx = zq_elems;

    static int attr_done = 0;
    if (!attr_done) {
        cudaFuncSetAttribute(vq_tc_kernel,
                             cudaFuncAttributeMaxDynamicSharedMemorySize, SMEM_TOTAL);
        attr_done = 1;
    }

    vq_prep_kernel<<<NE_ / 256, 256>>>(cb);
    vq_tc_kernel<<<NBLK, TPB, SMEM_TOTAL>>>(z, cb, out, write_zq, loss_idx);
}